// round 10
// baseline (speedup 1.0000x reference)
#include <cuda_runtime.h>
#include <cuda_bf16.h>

// JPEG q=99 luma-only path (chroma provably constant for grayscale-replicated input).
// Warp per channel; 8 lanes per 8x8 tile; register DCT/IDCT; smem conflict-free transposes.

#define C1f 0.98078528040323044913f
#define C2f 0.92387953251128675613f
#define C3f 0.83146961230254523708f
#define C4f 0.70710678118654752440f
#define C5f 0.55557023301960222474f
#define C6f 0.38268343236508977173f
#define C7f 0.19509032201612826785f

__constant__ float YQc[64] = {
    16.f, 11.f, 10.f, 16.f, 24.f, 40.f, 51.f, 61.f,
    12.f, 12.f, 14.f, 19.f, 26.f, 58.f, 60.f, 55.f,
    14.f, 13.f, 16.f, 24.f, 40.f, 57.f, 69.f, 56.f,
    14.f, 17.f, 22.f, 29.f, 51.f, 87.f, 80.f, 62.f,
    18.f, 22.f, 37.f, 56.f, 68.f,109.f,103.f, 77.f,
    24.f, 35.f, 55.f, 64.f, 81.f,104.f,113.f, 92.f,
    49.f, 64.f, 78.f, 87.f,103.f,121.f,120.f,101.f,
    72.f, 92.f, 95.f, 98.f,112.f,100.f,103.f, 99.f
};

__device__ __forceinline__ void dct8(const float in[8], float out[8]) {
    float s0 = in[0] + in[7], s1 = in[1] + in[6], s2 = in[2] + in[5], s3 = in[3] + in[4];
    float d0 = in[0] - in[7], d1 = in[1] - in[6], d2 = in[2] - in[5], d3 = in[3] - in[4];
    out[0] = (s0 + s3) + (s1 + s2);
    out[4] = C4f * ((s0 + s3) - (s1 + s2));
    out[2] = C2f*s0 + C6f*s1 - C6f*s2 - C2f*s3;
    out[6] = C6f*s0 - C2f*s1 + C2f*s2 - C6f*s3;
    out[1] = C1f*d0 + C3f*d1 + C5f*d2 + C7f*d3;
    out[3] = C3f*d0 - C7f*d1 - C1f*d2 - C5f*d3;
    out[5] = C5f*d0 - C1f*d1 + C7f*d2 + C3f*d3;
    out[7] = C7f*d0 - C5f*d1 + C3f*d2 - C1f*d3;
}

__device__ __forceinline__ void idct8(const float e[8], float out[8]) {
    float ev0 = e[0] + C2f*e[2] + C4f*e[4] + C6f*e[6];
    float ev1 = e[0] + C6f*e[2] - C4f*e[4] - C2f*e[6];
    float ev2 = e[0] - C6f*e[2] - C4f*e[4] + C2f*e[6];
    float ev3 = e[0] - C2f*e[2] + C4f*e[4] - C6f*e[6];
    float od0 = C1f*e[1] + C3f*e[3] + C5f*e[5] + C7f*e[7];
    float od1 = C3f*e[1] - C7f*e[3] - C1f*e[5] - C5f*e[7];
    float od2 = C5f*e[1] - C1f*e[3] + C7f*e[5] + C3f*e[7];
    float od3 = C7f*e[1] - C5f*e[3] + C3f*e[5] - C1f*e[7];
    out[0] = ev0 + od0;  out[7] = ev0 - od0;
    out[1] = ev1 + od1;  out[6] = ev1 - od1;
    out[2] = ev2 + od2;  out[5] = ev2 - od2;
    out[3] = ev3 + od3;  out[4] = ev3 - od3;
}

#define WARPS_BLK 8
#define STRIDE 200           // floats per warp in data buffer; 200*4 bytes, 16B aligned
#define TSTRIDE 33           // transpose buffer row stride (conflict-free both directions)

__global__ __launch_bounds__(256, 5)
void jpeg_y_kernel(const float* __restrict__ x, float* __restrict__ out, int nch)
{
    __shared__ float  shd [WARPS_BLK * STRIDE];        // staging in, reused for out
    __shared__ float  tbuf[WARPS_BLK * 8 * TSTRIDE];   // per-warp 8x32 transpose buffer
    __shared__ float2 qtab[64];                        // {0.25*aa/qs, qs*aa}

    const int tid  = threadIdx.x;
    const int lane = tid & 31;
    const int wrp  = tid >> 5;
    const int tile = lane >> 3;       // 0..3
    const int l    = lane & 7;        // row-in-tile / freq index
    const int br   = tile >> 1, bc = tile & 1;
    const int gch  = blockIdx.x * WARPS_BLK + wrp;
    const bool act = (gch < nch);
    const int base = wrp * STRIDE;
    const int tb   = wrp * 8 * TSTRIDE;

    // fused quant table (once per block)
    if (tid < 64) {
        int u = tid >> 3, v = tid & 7;
        float qv = YQc[tid] * 0.02f;                       // quality-99 factor
        float aa = ((u == 0) ? C4f : 1.0f) * ((v == 0) ? C4f : 1.0f);
        qtab[tid] = make_float2(0.25f * aa / qv, qv * aa);
    }

    // ---- stage channel (float4 coalesced) + min/max on the fly ----
    float mn = 3.4e38f, mx = -3.4e38f;
    if (act) {
        const float4* xp4 = (const float4*)(x + (size_t)gch * 196);
        float4* s4 = (float4*)(shd + base);
        #pragma unroll
        for (int k = 0; k < 2; k++) {
            int i = lane + 32 * k;
            if (i < 49) {
                float4 v = xp4[i];
                s4[i] = v;
                mn = fminf(mn, fminf(fminf(v.x, v.y), fminf(v.z, v.w)));
                mx = fmaxf(mx, fmaxf(fmaxf(v.x, v.y), fmaxf(v.z, v.w)));
            }
        }
    }
    __syncthreads();                  // table + staging visibility
    if (!act) return;

    #pragma unroll
    for (int o = 16; o; o >>= 1) {
        mn = fminf(mn, __shfl_xor_sync(0xffffffffu, mn, o));
        mx = fmaxf(mx, __shfl_xor_sync(0xffffffffu, mx, o));
    }
    const float rng = mx - mn + 1e-5f;
    const float sc  = 255.0f / rng;
    const float off = -mn * sc - 128.0f;   // w = v*sc + off

    // ---- pass 1: row DCT (lane = tile row, regs = y) ----
    float a[8];
    {
        const int row = min(max(8 * br + l - 1, 0), 13);
        float w[8];
        #pragma unroll
        for (int y = 0; y < 8; y++) {
            int col = min(max(8 * bc + y - 1, 0), 13);
            w[y] = fmaf(shd[base + row * 14 + col], sc, off);
        }
        dct8(w, a);                   // a[v]
    }

    // ---- transpose 1 (smem, conflict-free): lane = v, regs = x ----
    __syncwarp();
    #pragma unroll
    for (int v = 0; v < 8; v++) tbuf[tb + v * TSTRIDE + tile * 8 + l] = a[v];
    __syncwarp();
    #pragma unroll
    for (int j = 0; j < 8; j++) a[j] = tbuf[tb + l * TSTRIDE + tile * 8 + j];

    // ---- pass 2: column DCT + diff_round quant/dequant (fused table) ----
    {
        float d[8];
        dct8(a, d);                   // d[u], lane = v
        #pragma unroll
        for (int u = 0; u < 8; u++) {
            float2 t = qtab[u * 8 + l];
            float qd = d[u] * t.x;
            float rr = rintf(qd);     // round-half-even == jnp.round
            float dd = qd - rr;
            a[u] = (rr + dd * dd * dd) * t.y;
        }
    }

    // ---- pass 3: IDCT over u (regs), lane = v ----
    {
        float t[8];
        idct8(a, t);
        #pragma unroll
        for (int i = 0; i < 8; i++) a[i] = t[i];   // a[x]
    }

    // ---- transpose 2: lane = x, regs = v ----
    __syncwarp();
    #pragma unroll
    for (int v = 0; v < 8; v++) tbuf[tb + v * TSTRIDE + tile * 8 + l] = a[v];
    __syncwarp();
    #pragma unroll
    for (int j = 0; j < 8; j++) a[j] = tbuf[tb + l * TSTRIDE + tile * 8 + j];

    // ---- pass 4: IDCT over v + crop/clip/denorm -> shd (reuse input buffer) ----
    {
        float p[8];
        idct8(a, p);                  // p[y], lane = tile row x
        const float dsc = rng * (1.0f / 255.0f);
        const int i = 8 * br + l - 1;
        if ((unsigned)i < 14u) {
            #pragma unroll
            for (int y = 0; y < 8; y++) {
                int j = 8 * bc + y - 1;
                if ((unsigned)j < 14u) {
                    float pv = 0.25f * p[y] + 128.0f;
                    pv = fminf(fmaxf(pv, 0.0f), 255.0f);
                    shd[base + i * 14 + j] = pv * dsc + mn;
                }
            }
        }
    }
    __syncwarp();

    // ---- de-stage output (float4 coalesced) ----
    {
        float4* op4 = (float4*)(out + (size_t)gch * 196);
        const float4* s4 = (const float4*)(shd + base);
        #pragma unroll
        for (int k = 0; k < 2; k++) {
            int i = lane + 32 * k;
            if (i < 49) op4[i] = s4[i];
        }
    }
}

extern "C" void kernel_launch(void* const* d_in, const int* in_sizes, int n_in,
                              void* d_out, int out_size)
{
    const float* x = (const float*)d_in[0];
    float* out = (float*)d_out;
    int nch = in_sizes[0] / 196;                      // 32*1024 channels of 14x14
    int blocks = (nch + WARPS_BLK - 1) / WARPS_BLK;   // 4096
    jpeg_y_kernel<<<blocks, 256>>>(x, out, nch);
}

// round 12
// speedup vs baseline: 1.3835x; 1.3835x over previous
#include <cuda_runtime.h>
#include <cuda_bf16.h>

// JPEG q=99 luma-only path (chroma provably constant for grayscale-replicated input).
// Thread-per-8x8-tile (register transforms, literal constants), warp-autonomous:
// each warp owns 8 channels; float4 staging; no block-wide barriers.

#define C1f 0.98078528040323044913f
#define C2f 0.92387953251128675613f
#define C3f 0.83146961230254523708f
#define C4f 0.70710678118654752440f
#define C5f 0.55557023301960222474f
#define C6f 0.38268343236508977173f
#define C7f 0.19509032201612826785f

__device__ __forceinline__ void dct8(const float in[8], float out[8]) {
    float s0 = in[0] + in[7], s1 = in[1] + in[6], s2 = in[2] + in[5], s3 = in[3] + in[4];
    float d0 = in[0] - in[7], d1 = in[1] - in[6], d2 = in[2] - in[5], d3 = in[3] - in[4];
    out[0] = (s0 + s3) + (s1 + s2);
    out[4] = C4f * ((s0 + s3) - (s1 + s2));
    out[2] = C2f*s0 + C6f*s1 - C6f*s2 - C2f*s3;
    out[6] = C6f*s0 - C2f*s1 + C2f*s2 - C6f*s3;
    out[1] = C1f*d0 + C3f*d1 + C5f*d2 + C7f*d3;
    out[3] = C3f*d0 - C7f*d1 - C1f*d2 - C5f*d3;
    out[5] = C5f*d0 - C1f*d1 + C7f*d2 + C3f*d3;
    out[7] = C7f*d0 - C5f*d1 + C3f*d2 - C1f*d3;
}

__device__ __forceinline__ void idct8(const float e[8], float out[8]) {
    float ev0 = e[0] + C2f*e[2] + C4f*e[4] + C6f*e[6];
    float ev1 = e[0] + C6f*e[2] - C4f*e[4] - C2f*e[6];
    float ev2 = e[0] - C6f*e[2] - C4f*e[4] + C2f*e[6];
    float ev3 = e[0] - C2f*e[2] + C4f*e[4] - C6f*e[6];
    float od0 = C1f*e[1] + C3f*e[3] + C5f*e[5] + C7f*e[7];
    float od1 = C3f*e[1] - C7f*e[3] - C1f*e[5] - C5f*e[7];
    float od2 = C5f*e[1] - C1f*e[3] + C7f*e[5] + C3f*e[7];
    float od3 = C7f*e[1] - C5f*e[3] + C3f*e[5] - C1f*e[7];
    out[0] = ev0 + od0;  out[7] = ev0 - od0;
    out[1] = ev1 + od1;  out[6] = ev1 - od1;
    out[2] = ev2 + od2;  out[5] = ev2 - od2;
    out[3] = ev3 + od3;  out[4] = ev3 - od3;
}

#define CH_STRIDE 200    // floats per channel buffer (196 used; 50 float4, 16B aligned)
#define WARPS_BLK 4

__global__ __launch_bounds__(128, 4)
void jpeg_y_kernel(const float* __restrict__ x, float* __restrict__ out, int nch)
{
    constexpr float YQT[64] = {
        16.f, 11.f, 10.f, 16.f, 24.f, 40.f, 51.f, 61.f,
        12.f, 12.f, 14.f, 19.f, 26.f, 58.f, 60.f, 55.f,
        14.f, 13.f, 16.f, 24.f, 40.f, 57.f, 69.f, 56.f,
        14.f, 17.f, 22.f, 29.f, 51.f, 87.f, 80.f, 62.f,
        18.f, 22.f, 37.f, 56.f, 68.f,109.f,103.f, 77.f,
        24.f, 35.f, 55.f, 64.f, 81.f,104.f,113.f, 92.f,
        49.f, 64.f, 78.f, 87.f,103.f,121.f,120.f,101.f,
        72.f, 92.f, 95.f, 98.f,112.f,100.f,103.f, 99.f
    };
    constexpr float AL[8] = { C4f, 1.f, 1.f, 1.f, 1.f, 1.f, 1.f, 1.f };

    __shared__ float shd[WARPS_BLK * 8 * CH_STRIDE];   // 25.6 KB

    const int lane = threadIdx.x & 31;
    const int wrp  = threadIdx.x >> 5;
    const int chs  = lane >> 2;          // channel slot within warp (0..7)
    const int tile = lane & 3;           // tile within channel
    const int br   = tile >> 1, bc = tile & 1;
    const int gch0 = (blockIdx.x * WARPS_BLK + wrp) * 8;
    float* sb = shd + wrp * (8 * CH_STRIDE);

    // ---- stage 8 channels (float4, warp-coalesced, division-free) ----
    #pragma unroll
    for (int c = 0; c < 8; c++) {
        if (gch0 + c < nch) {
            const float4* xp4 = (const float4*)(x + (size_t)(gch0 + c) * 196);
            float4* s4 = (float4*)(sb + c * CH_STRIDE);
            s4[lane] = xp4[lane];
            if (lane < 17) s4[lane + 32] = xp4[lane + 32];
        }
    }
    __syncwarp();

    // ---- per-channel min/max (4 lanes/channel, float4 scan + shuffle) ----
    const float* cb = sb + chs * CH_STRIDE;
    {
    }
    float mn = 3.4e38f, mx = -3.4e38f;
    {
        const float4* cb4 = (const float4*)cb;
        #pragma unroll
        for (int k = 0; k < 13; k++) {
            int i = tile + 4 * k;
            if (i < 49) {
                float4 v = cb4[i];
                mn = fminf(mn, fminf(fminf(v.x, v.y), fminf(v.z, v.w)));
                mx = fmaxf(mx, fmaxf(fmaxf(v.x, v.y), fmaxf(v.z, v.w)));
            }
        }
    }
    mn = fminf(mn, __shfl_xor_sync(0xffffffffu, mn, 1));
    mx = fmaxf(mx, __shfl_xor_sync(0xffffffffu, mx, 1));
    mn = fminf(mn, __shfl_xor_sync(0xffffffffu, mn, 2));
    mx = fmaxf(mx, __shfl_xor_sync(0xffffffffu, mx, 2));
    const float rng = mx - mn + 1e-5f;
    const float sc  = 255.0f / rng;
    const float off = -mn * sc - 128.0f;     // w = v*sc + off

    float A[64];

    // ---- pass 1: row DCT (over y) from padded window ----
    #pragma unroll
    for (int xr = 0; xr < 8; xr++) {
        int row = min(max(8 * br + xr - 1, 0), 13);
        float w[8], r[8];
        #pragma unroll
        for (int y = 0; y < 8; y++) {
            int col = min(max(8 * bc + y - 1, 0), 13);
            w[y] = fmaf(cb[row * 14 + col], sc, off);
        }
        dct8(w, r);
        #pragma unroll
        for (int v = 0; v < 8; v++) A[xr * 8 + v] = r[v];
    }

    // ---- pass 2: column DCT + diff_round quant/dequant (literal fused consts) ----
    #pragma unroll
    for (int v = 0; v < 8; v++) {
        float c[8], d[8];
        #pragma unroll
        for (int xr = 0; xr < 8; xr++) c[xr] = A[xr * 8 + v];
        dct8(c, d);
        #pragma unroll
        for (int u = 0; u < 8; u++) {
            const float aa = AL[u] * AL[v];
            const float qs = YQT[u * 8 + v] * 0.02f;
            const float iq = 0.25f * aa / qs;     // folds to literal
            const float dq = qs * aa;             // folds to literal
            float qd = d[u] * iq;
            float rr = rintf(qd);                 // round-half-even == jnp.round
            float dd = qd - rr;
            A[u * 8 + v] = (rr + dd * dd * dd) * dq;
        }
    }

    // ---- pass 3: IDCT over u (columns) ----
    #pragma unroll
    for (int v = 0; v < 8; v++) {
        float c[8], s[8];
        #pragma unroll
        for (int u = 0; u < 8; u++) c[u] = A[u * 8 + v];
        idct8(c, s);
        #pragma unroll
        for (int xr = 0; xr < 8; xr++) A[xr * 8 + v] = s[xr];
    }

    __syncwarp();    // all window reads complete before output overwrites

    // ---- pass 4: IDCT over v + crop/clip/denorm -> shared (reuse buffer) ----
    {
        const float dsc = rng * (1.0f / 255.0f);
        float* cbw = sb + chs * CH_STRIDE;
        #pragma unroll
        for (int xr = 0; xr < 8; xr++) {
            int i = 8 * br + xr - 1;
            if ((unsigned)i < 14u) {
                float e[8], p[8];
                #pragma unroll
                for (int v = 0; v < 8; v++) e[v] = A[xr * 8 + v];
                idct8(e, p);
                #pragma unroll
                for (int y = 0; y < 8; y++) {
                    int j = 8 * bc + y - 1;
                    if ((unsigned)j < 14u) {
                        float pv = 0.25f * p[y] + 128.0f;
                        pv = fminf(fmaxf(pv, 0.0f), 255.0f);
                        cbw[i * 14 + j] = pv * dsc + mn;
                    }
                }
            }
        }
    }
    __syncwarp();

    // ---- de-stage 8 channels (float4, warp-coalesced) ----
    #pragma unroll
    for (int c = 0; c < 8; c++) {
        if (gch0 + c < nch) {
            float4* op4 = (float4*)(out + (size_t)(gch0 + c) * 196);
            const float4* s4 = (const float4*)(sb + c * CH_STRIDE);
            op4[lane] = s4[lane];
            if (lane < 17) op4[lane + 32] = s4[lane + 32];
        }
    }
}

extern "C" void kernel_launch(void* const* d_in, const int* in_sizes, int n_in,
                              void* d_out, int out_size)
{
    const float* x = (const float*)d_in[0];
    float* out = (float*)d_out;
    int nch = in_sizes[0] / 196;                 // 32*1024 channels of 14x14
    int chb = WARPS_BLK * 8;                     // 32 channels per block
    int blocks = (nch + chb - 1) / chb;          // 1024
    jpeg_y_kernel<<<blocks, 128>>>(x, out, nch);
}